// round 7
// baseline (speedup 1.0000x reference)
#include <cuda_runtime.h>

#define NN 8192
#define VV 8
#define OO 16
#define HH 128
#define ROW (4*VV + 3*OO)   // 80 floats per input row
#define TPB 128
#define WPB 4               // warps per block (1 warp = 1 problem row n)
#define NPART (NN / WPB)    // 2048 blocks
#define BUFCAP 64           // power-of-2 smem ring per warp

// Per-block partials (plain stores; no zeroing kernel)
__device__ float g_pd[NPART];
__device__ float g_po[NPART];
__device__ float g_pv[NPART];
__device__ int   g_oc[NPART];
__device__ int   g_vc[NPART];
__device__ unsigned int g_done;   // zero-init; last block resets each launch

__inline__ __device__ float warp_red_f(float v) {
    #pragma unroll
    for (int o = 16; o > 0; o >>= 1) v += __shfl_down_sync(0xffffffffu, v, o);
    return v;
}
__inline__ __device__ int warp_red_i(int v) {
    #pragma unroll
    for (int o = 16; o > 0; o >>= 1) v += __shfl_down_sync(0xffffffffu, v, o);
    return v;
}

// Warp layout: lane = v*4 + ch. Vehicle v, chunk ch of 32 h-steps.
// One warp = one n => obstacle data, prune box, ring-buffer state warp-uniform.
__global__ void __launch_bounds__(TPB) loss_kernel(
    const float* __restrict__ pred,     // (N, V, H) f32
    const float* __restrict__ inputs,   // (N, 80) f32
    float* __restrict__ out)
{
    const int warp = threadIdx.x >> 5;
    const int lane = threadIdx.x & 31;
    const int n  = blockIdx.x * WPB + warp;
    const int v  = lane >> 2;
    const int ch = lane & 3;

    const float* row = inputs + (size_t)n * ROW;

    __shared__ float  s_ox[WPB][OO], s_oy[WPB][OO], s_r2[WPB][OO];
    __shared__ float2 s_cum[WPB][16][32];   // within-chunk cumulative pos, odd steps
    __shared__ float2 s_buf[WPB][BUFCAP];   // drain ring

    // ---- obstacles -> smem; prune box via warp reductions ----
    float lcx = 0.0f, lcy = 0.0f, lr = 0.0f;
    if (lane < OO) {
        lcx = row[4*VV + 3*lane + 0];
        lcy = row[4*VV + 3*lane + 1];
        lr  = row[4*VV + 3*lane + 2] + 1.0f;     // + OBST_RADIUS
        s_ox[warp][lane] = lcx;
        s_oy[warp][lane] = lcy;
        s_r2[warp][lane] = (lr > 0.0f) ? lr * lr : -1.0f;
    }
    float mnx = (lane < OO) ? lcx :  1e30f;
    float mxx = (lane < OO) ? lcx : -1e30f;
    float mny = (lane < OO) ? lcy :  1e30f;
    float mxy = (lane < OO) ? lcy : -1e30f;
    float rmx = (lane < OO) ? lr  : -1e30f;
    #pragma unroll
    for (int o = 16; o > 0; o >>= 1) {
        mnx = fminf(mnx, __shfl_xor_sync(0xffffffffu, mnx, o));
        mxx = fmaxf(mxx, __shfl_xor_sync(0xffffffffu, mxx, o));
        mny = fminf(mny, __shfl_xor_sync(0xffffffffu, mny, o));
        mxy = fmaxf(mxy, __shfl_xor_sync(0xffffffffu, mxy, o));
        rmx = fmaxf(rmx, __shfl_xor_sync(0xffffffffu, rmx, o));
    }
    __syncwarp();
    const float cbx = 0.5f * (mnx + mxx), hbx = 0.5f * (mxx - mnx) + rmx;
    const float cby = 0.5f * (mny + mxy), hby = 0.5f * (mxy - mny) + rmx;

    const float x0 = row[4*v + 0];
    const float y0 = row[4*v + 1];
    const float tx = row[4*v + 2];
    const float ty = row[4*v + 3];

    const float4* p4 =
        (const float4*)(pred + ((size_t)(n * VV + v) * HH + ch * 32));

    // ---- pass 1: scaled cumulative step vectors; cache odd steps ----
    float cx = 0.0f, cy = 0.0f;
    #pragma unroll
    for (int i = 0; i < 8; ++i) {
        float4 p = p4[i];
        float s, c;
        __sincosf(p.x, &s, &c); cx = fmaf(2.0f, c, cx); cy = fmaf(2.0f, s, cy);
        __sincosf(p.y, &s, &c); cx = fmaf(2.0f, c, cx); cy = fmaf(2.0f, s, cy);
        s_cum[warp][2*i][lane] = make_float2(cx, cy);        // after step 4i+1
        __sincosf(p.z, &s, &c); cx = fmaf(2.0f, c, cx); cy = fmaf(2.0f, s, cy);
        __sincosf(p.w, &s, &c); cx = fmaf(2.0f, c, cx); cy = fmaf(2.0f, s, cy);
        s_cum[warp][2*i+1][lane] = make_float2(cx, cy);      // after step 4i+3
    }

    // segmented exclusive prefix over the 4 chunk-lanes of each vehicle
    float ix = cx, iy = cy, t;
    t = __shfl_up_sync(0xffffffffu, ix, 1, 4); if (ch >= 1) ix += t;
    t = __shfl_up_sync(0xffffffffu, iy, 1, 4); if (ch >= 1) iy += t;
    t = __shfl_up_sync(0xffffffffu, ix, 2, 4); if (ch >= 2) ix += t;
    t = __shfl_up_sync(0xffffffffu, iy, 2, 4); if (ch >= 2) iy += t;
    const float basex = x0 + (ix - cx);     // cum already carries STEP=2
    const float basey = y0 + (iy - cy);

    // ---- pass 2: positions from cache; compact in-box; drain inline ----
    float dist_sum = 0.0f, oinv = 0.0f, vinv = 0.0f;
    int ocnt = 0, vcnt = 0;
    int head = 0, pending = 0;              // warp-uniform ring state
    const unsigned lt_mask = (1u << lane) - 1u;
    const bool vact = (v < 7);

    auto process = [&](float px, float py) {
        // target-distance term
        float dx = tx - px, dy = ty - py;
        float td2 = fmaxf(fmaf(dx, dx, dy * dy), 1e-30f);
        dist_sum += td2 * rsqrtf(td2);

        // in-box -> compact append to ring
        bool inbox = (fabsf(px - cbx) <= hbx) & (fabsf(py - cby) <= hby);
        unsigned m = __ballot_sync(0xffffffffu, inbox);
        if (inbox)
            s_buf[warp][(head + pending + __popc(m & lt_mask)) & (BUFCAP-1)] =
                make_float2(px, py);
        pending += __popc(m);

        // vehicle-vehicle term: vehicle v+1 same chunk = lane+4
        float xn = __shfl_down_sync(0xffffffffu, px, 4);
        float yn = __shfl_down_sync(0xffffffffu, py, 4);
        if (vact) {
            float bxv = xn - px, byv = yn - py;
            float d2 = fmaf(bxv, bxv, byv * byv);
            if (d2 < 1.0f) { vinv += rsqrtf(d2); vcnt++; }   // VEH_R^2 = 1
        }

        // dense drain of 32 points (warp-uniform branch)
        if (pending >= 32) {
            __syncwarp();
            float2 q = s_buf[warp][(head + lane) & (BUFCAP-1)];
            #pragma unroll
            for (int o = 0; o < OO; ++o) {
                float ax = q.x - s_ox[warp][o];
                float ay = q.y - s_oy[warp][o];
                float d2o = fmaf(ax, ax, ay * ay);
                if (d2o < s_r2[warp][o]) { oinv += rsqrtf(d2o); ocnt++; }
            }
            head = (head + 32) & (BUFCAP-1);
            pending -= 32;
        }
    };

    float prevx = basex, prevy = basey;     // position after step -1
    #pragma unroll 1
    for (int i = 0; i < 8; ++i) {
        float4 p = p4[i];
        float2 cum0 = s_cum[warp][2*i][lane];
        float2 cum1 = s_cum[warp][2*i+1][lane];
        float s0, c0, s2, c2;
        __sincosf(p.x, &s0, &c0);
        __sincosf(p.z, &s2, &c2);

        float xA = fmaf(2.0f, c0, prevx), yA = fmaf(2.0f, s0, prevy); // 4i
        float xB = basex + cum0.x,        yB = basey + cum0.y;        // 4i+1
        float xC = fmaf(2.0f, c2, xB),    yC = fmaf(2.0f, s2, yB);    // 4i+2
        float xD = basex + cum1.x,        yD = basey + cum1.y;        // 4i+3
        prevx = xD; prevy = yD;

        process(xA, yA);
        process(xB, yB);
        process(xC, yC);
        process(xD, yD);
    }

    // final flush of the partial ring
    if (pending > 0) {
        __syncwarp();
        if (lane < pending) {
            float2 q = s_buf[warp][(head + lane) & (BUFCAP-1)];
            #pragma unroll
            for (int o = 0; o < OO; ++o) {
                float ax = q.x - s_ox[warp][o];
                float ay = q.y - s_oy[warp][o];
                float d2o = fmaf(ax, ax, ay * ay);
                if (d2o < s_r2[warp][o]) { oinv += rsqrtf(d2o); ocnt++; }
            }
        }
    }

    // ---- warp -> block reduction ----
    dist_sum = warp_red_f(dist_sum);
    oinv     = warp_red_f(oinv);
    vinv     = warp_red_f(vinv);
    ocnt     = warp_red_i(ocnt);
    vcnt     = warp_red_i(vcnt);

    __shared__ float sd[WPB], so[WPB], sv[WPB];
    __shared__ int soc[WPB], svc[WPB];
    if (lane == 0) {
        sd[warp] = dist_sum; so[warp] = oinv; sv[warp] = vinv;
        soc[warp] = ocnt; svc[warp] = vcnt;
    }
    __syncthreads();
    if (warp == 0) {
        float d = (lane < WPB) ? sd[lane] : 0.0f;
        float a = (lane < WPB) ? so[lane] : 0.0f;
        float b = (lane < WPB) ? sv[lane] : 0.0f;
        int   c = (lane < WPB) ? soc[lane] : 0;
        int   e = (lane < WPB) ? svc[lane] : 0;
        d = warp_red_f(d); a = warp_red_f(a); b = warp_red_f(b);
        c = warp_red_i(c); e = warp_red_i(e);
        if (lane == 0) {
            g_pd[blockIdx.x] = d;
            g_po[blockIdx.x] = a;
            g_pv[blockIdx.x] = b;
            g_oc[blockIdx.x] = c;
            g_vc[blockIdx.x] = e;
        }
    }

    // ---- last-block finalize ----
    __shared__ bool isLast;
    __threadfence();
    if (threadIdx.x == 0) {
        unsigned int prev = atomicAdd(&g_done, 1u);
        isLast = (prev == NPART - 1);
    }
    __syncthreads();
    if (!isLast) return;

    float d = 0.0f, a = 0.0f, b = 0.0f;
    int c = 0, e = 0;
    #pragma unroll
    for (int i = 0; i < NPART / TPB; ++i) {
        int idx = threadIdx.x + i * TPB;
        d += g_pd[idx]; a += g_po[idx]; b += g_pv[idx];
        c += g_oc[idx]; e += g_vc[idx];
    }
    d = warp_red_f(d); a = warp_red_f(a); b = warp_red_f(b);
    c = warp_red_i(c); e = warp_red_i(e);
    if (lane == 0) {
        sd[warp] = d; so[warp] = a; sv[warp] = b; soc[warp] = c; svc[warp] = e;
    }
    __syncthreads();
    if (warp == 0) {
        d = (lane < WPB) ? sd[lane] : 0.0f;
        a = (lane < WPB) ? so[lane] : 0.0f;
        b = (lane < WPB) ? sv[lane] : 0.0f;
        c = (lane < WPB) ? soc[lane] : 0;
        e = (lane < WPB) ? svc[lane] : 0;
        d = warp_red_f(d); a = warp_red_f(a); b = warp_red_f(b);
        c = warp_red_i(c); e = warp_red_i(e);
        if (lane == 0) {
            double loss = (double)d / ((double)NN * VV * HH);   // DIST_COST=1
            if (c > 0) loss += ((double)a / (double)c) * 0.1;   // OBST_COST
            if (e > 0) loss += ((double)b / (double)e) * 0.1;   // VEH_COST
            out[0] = (float)loss;
            g_done = 0;   // reset for next graph replay
        }
    }
}

extern "C" void kernel_launch(void* const* d_in, const int* in_sizes, int n_in,
                              void* d_out, int out_size) {
    const float* pred   = (const float*)d_in[0];   // (N, V, H, 1) f32
    const float* inputs = (const float*)d_in[1];   // (N, 80) f32
    float* out = (float*)d_out;

    loss_kernel<<<NPART, TPB>>>(pred, inputs, out);
}

// round 8
// speedup vs baseline: 1.1755x; 1.1755x over previous
#include <cuda_runtime.h>

#define NN 8192
#define VV 8
#define OO 16
#define HH 128
#define ROW (4*VV + 3*OO)   // 80 floats per input row
#define TPB 256
#define WPB 8               // warps per block (1 warp = 1 problem row n)
#define NPART (NN / WPB)    // 1024 blocks
#define BUFCAP 64           // power-of-2 smem ring per warp

// Per-block partials (plain stores; no zeroing kernel)
__device__ float g_pd[NPART];
__device__ float g_po[NPART];
__device__ float g_pv[NPART];
__device__ int   g_oc[NPART];
__device__ int   g_vc[NPART];
__device__ unsigned int g_done;   // zero-init; last block resets each launch

__inline__ __device__ float warp_red_f(float v) {
    #pragma unroll
    for (int o = 16; o > 0; o >>= 1) v += __shfl_down_sync(0xffffffffu, v, o);
    return v;
}
__inline__ __device__ int warp_red_i(int v) {
    #pragma unroll
    for (int o = 16; o > 0; o >>= 1) v += __shfl_down_sync(0xffffffffu, v, o);
    return v;
}

__inline__ __device__ float fast_sqrt(float x) {
    float r;
    asm("sqrt.approx.f32 %0, %1;" : "=f"(r) : "f"(x));
    return r;
}

// Warp layout: lane = v*4 + ch. Vehicle v, chunk ch of 32 h-steps.
// One warp = one n => obstacle data, prune box, ring state warp-uniform.
__global__ void __launch_bounds__(TPB) loss_kernel(
    const float* __restrict__ pred,     // (N, V, H) f32
    const float* __restrict__ inputs,   // (N, 80) f32
    float* __restrict__ out)
{
    const int warp = threadIdx.x >> 5;
    const int lane = threadIdx.x & 31;
    const int n  = blockIdx.x * WPB + warp;
    const int v  = lane >> 2;
    const int ch = lane & 3;

    const float* row = inputs + (size_t)n * ROW;

    __shared__ unsigned long long s_onxy[WPB][OO];  // packed (-ox,-oy) f32x2
    __shared__ float  s_r2[WPB][OO];
    __shared__ float2 s_buf[WPB][BUFCAP];           // drain ring

    // ---- obstacles -> smem; prune box via warp reductions ----
    float lcx = 0.0f, lcy = 0.0f, lr = 0.0f;
    if (lane < OO) {
        lcx = row[4*VV + 3*lane + 0];
        lcy = row[4*VV + 3*lane + 1];
        lr  = row[4*VV + 3*lane + 2] + 1.0f;     // + OBST_RADIUS
        unsigned long long packed;
        float nx = -lcx, ny = -lcy;
        asm("mov.b64 %0, {%1, %2};" : "=l"(packed) : "f"(nx), "f"(ny));
        s_onxy[warp][lane] = packed;
        s_r2[warp][lane] = (lr > 0.0f) ? lr * lr : -1.0f;
    }
    float mnx = (lane < OO) ? lcx :  1e30f;
    float mxx = (lane < OO) ? lcx : -1e30f;
    float mny = (lane < OO) ? lcy :  1e30f;
    float mxy = (lane < OO) ? lcy : -1e30f;
    float rmx = (lane < OO) ? lr  : -1e30f;
    #pragma unroll
    for (int o = 16; o > 0; o >>= 1) {
        mnx = fminf(mnx, __shfl_xor_sync(0xffffffffu, mnx, o));
        mxx = fmaxf(mxx, __shfl_xor_sync(0xffffffffu, mxx, o));
        mny = fminf(mny, __shfl_xor_sync(0xffffffffu, mny, o));
        mxy = fmaxf(mxy, __shfl_xor_sync(0xffffffffu, mxy, o));
        rmx = fmaxf(rmx, __shfl_xor_sync(0xffffffffu, rmx, o));
    }
    __syncwarp();
    const float cbx = 0.5f * (mnx + mxx), hbx = 0.5f * (mxx - mnx) + rmx;
    const float cby = 0.5f * (mny + mxy), hby = 0.5f * (mxy - mny) + rmx;

    const float x0 = row[4*v + 0];
    const float y0 = row[4*v + 1];
    const float tx = row[4*v + 2];
    const float ty = row[4*v + 3];

    const float4* p4 =
        (const float4*)(pred + ((size_t)(n * VV + v) * HH + ch * 32));

    // ---- pass 1: chunk sums of cos/sin ----
    float sx = 0.0f, sy = 0.0f;
    #pragma unroll
    for (int i = 0; i < 8; ++i) {
        float4 p = p4[i];
        float s, c;
        __sincosf(p.x, &s, &c); sx += c; sy += s;
        __sincosf(p.y, &s, &c); sx += c; sy += s;
        __sincosf(p.z, &s, &c); sx += c; sy += s;
        __sincosf(p.w, &s, &c); sx += c; sy += s;
    }
    // segmented exclusive prefix over the 4 chunk-lanes of each vehicle
    float ix = sx, iy = sy, t;
    t = __shfl_up_sync(0xffffffffu, ix, 1, 4); if (ch >= 1) ix += t;
    t = __shfl_up_sync(0xffffffffu, iy, 1, 4); if (ch >= 1) iy += t;
    t = __shfl_up_sync(0xffffffffu, ix, 2, 4); if (ch >= 2) ix += t;
    t = __shfl_up_sync(0xffffffffu, iy, 2, 4); if (ch >= 2) iy += t;
    float x = fmaf(2.0f, ix - sx, x0);   // STEP = 2
    float y = fmaf(2.0f, iy - sy, y0);

    // ---- pass 2: walk 32 steps; compact in-box; drain inline ----
    float dist_sum = 0.0f, oinv = 0.0f, vinv = 0.0f;
    int ocnt = 0, vcnt = 0;
    int head = 0, pending = 0;              // warp-uniform ring state
    const unsigned lt_mask = (1u << lane) - 1u;
    const bool vact = (v < 7);

    #pragma unroll 1
    for (int i = 0; i < 8; ++i) {
        float4 p = p4[i];
        float pv[4] = {p.x, p.y, p.z, p.w};
        #pragma unroll
        for (int j = 0; j < 4; ++j) {
            float s, c;
            __sincosf(pv[j], &s, &c);
            x = fmaf(2.0f, c, x);
            y = fmaf(2.0f, s, y);

            // target-distance term (sqrt.approx: no eps guard needed)
            float dx = tx - x, dy = ty - y;
            dist_sum += fast_sqrt(fmaf(dx, dx, dy * dy));

            // in-box -> compact append to ring
            bool inbox = (fabsf(x - cbx) <= hbx) & (fabsf(y - cby) <= hby);
            unsigned m = __ballot_sync(0xffffffffu, inbox);
            if (inbox)
                s_buf[warp][(head + pending + __popc(m & lt_mask)) & (BUFCAP-1)] =
                    make_float2(x, y);
            pending += __popc(m);

            // vehicle-vehicle term: vehicle v+1 same chunk = lane+4
            float xn = __shfl_down_sync(0xffffffffu, x, 4);
            float yn = __shfl_down_sync(0xffffffffu, y, 4);
            if (vact) {
                float bxv = xn - x, byv = yn - y;
                float d2 = fmaf(bxv, bxv, byv * byv);
                if (d2 < 1.0f) { vinv += rsqrtf(d2); vcnt++; }  // VEH_R^2 = 1
            }

            // dense drain of 32 points (warp-uniform branch; f32x2 math)
            if (pending >= 32) {
                __syncwarp();
                float2 q = s_buf[warp][(head + lane) & (BUFCAP-1)];
                unsigned long long pq;
                asm("mov.b64 %0, {%1, %2};" : "=l"(pq) : "f"(q.x), "f"(q.y));
                #pragma unroll
                for (int o = 0; o < OO; ++o) {
                    unsigned long long nob = s_onxy[warp][o];
                    unsigned long long dif, sq;
                    asm("add.rn.f32x2 %0, %1, %2;" : "=l"(dif) : "l"(pq), "l"(nob));
                    asm("mul.rn.f32x2 %0, %1, %2;" : "=l"(sq)  : "l"(dif), "l"(dif));
                    float qx_, qy_;
                    asm("mov.b64 {%0, %1}, %2;" : "=f"(qx_), "=f"(qy_) : "l"(sq));
                    float d2o = qx_ + qy_;
                    if (d2o < s_r2[warp][o]) { oinv += rsqrtf(d2o); ocnt++; }
                }
                head = (head + 32) & (BUFCAP-1);
                pending -= 32;
            }
        }
    }

    // final flush of the partial ring
    if (pending > 0) {
        __syncwarp();
        if (lane < pending) {
            float2 q = s_buf[warp][(head + lane) & (BUFCAP-1)];
            unsigned long long pq;
            asm("mov.b64 %0, {%1, %2};" : "=l"(pq) : "f"(q.x), "f"(q.y));
            #pragma unroll
            for (int o = 0; o < OO; ++o) {
                unsigned long long nob = s_onxy[warp][o];
                unsigned long long dif, sq;
                asm("add.rn.f32x2 %0, %1, %2;" : "=l"(dif) : "l"(pq), "l"(nob));
                asm("mul.rn.f32x2 %0, %1, %2;" : "=l"(sq)  : "l"(dif), "l"(dif));
                float qx_, qy_;
                asm("mov.b64 {%0, %1}, %2;" : "=f"(qx_), "=f"(qy_) : "l"(sq));
                float d2o = qx_ + qy_;
                if (d2o < s_r2[warp][o]) { oinv += rsqrtf(d2o); ocnt++; }
            }
        }
    }

    // ---- warp -> block reduction ----
    dist_sum = warp_red_f(dist_sum);
    oinv     = warp_red_f(oinv);
    vinv     = warp_red_f(vinv);
    ocnt     = warp_red_i(ocnt);
    vcnt     = warp_red_i(vcnt);

    __shared__ float sd[WPB], so[WPB], sv[WPB];
    __shared__ int soc[WPB], svc[WPB];
    if (lane == 0) {
        sd[warp] = dist_sum; so[warp] = oinv; sv[warp] = vinv;
        soc[warp] = ocnt; svc[warp] = vcnt;
    }
    __syncthreads();
    if (warp == 0) {
        float d = (lane < WPB) ? sd[lane] : 0.0f;
        float a = (lane < WPB) ? so[lane] : 0.0f;
        float b = (lane < WPB) ? sv[lane] : 0.0f;
        int   c = (lane < WPB) ? soc[lane] : 0;
        int   e = (lane < WPB) ? svc[lane] : 0;
        d = warp_red_f(d); a = warp_red_f(a); b = warp_red_f(b);
        c = warp_red_i(c); e = warp_red_i(e);
        if (lane == 0) {
            g_pd[blockIdx.x] = d;
            g_po[blockIdx.x] = a;
            g_pv[blockIdx.x] = b;
            g_oc[blockIdx.x] = c;
            g_vc[blockIdx.x] = e;
        }
    }

    // ---- last-block finalize ----
    __shared__ bool isLast;
    __threadfence();
    if (threadIdx.x == 0) {
        unsigned int prev = atomicAdd(&g_done, 1u);
        isLast = (prev == NPART - 1);
    }
    __syncthreads();
    if (!isLast) return;

    float d = 0.0f, a = 0.0f, b = 0.0f;
    int c = 0, e = 0;
    #pragma unroll
    for (int i = 0; i < NPART / TPB; ++i) {
        int idx = threadIdx.x + i * TPB;
        d += g_pd[idx]; a += g_po[idx]; b += g_pv[idx];
        c += g_oc[idx]; e += g_vc[idx];
    }
    d = warp_red_f(d); a = warp_red_f(a); b = warp_red_f(b);
    c = warp_red_i(c); e = warp_red_i(e);
    if (lane == 0) {
        sd[warp] = d; so[warp] = a; sv[warp] = b; soc[warp] = c; svc[warp] = e;
    }
    __syncthreads();
    if (warp == 0) {
        d = (lane < WPB) ? sd[lane] : 0.0f;
        a = (lane < WPB) ? so[lane] : 0.0f;
        b = (lane < WPB) ? sv[lane] : 0.0f;
        c = (lane < WPB) ? soc[lane] : 0;
        e = (lane < WPB) ? svc[lane] : 0;
        d = warp_red_f(d); a = warp_red_f(a); b = warp_red_f(b);
        c = warp_red_i(c); e = warp_red_i(e);
        if (lane == 0) {
            double loss = (double)d / ((double)NN * VV * HH);   // DIST_COST=1
            if (c > 0) loss += ((double)a / (double)c) * 0.1;   // OBST_COST
            if (e > 0) loss += ((double)b / (double)e) * 0.1;   // VEH_COST
            out[0] = (float)loss;
            g_done = 0;   // reset for next graph replay
        }
    }
}

extern "C" void kernel_launch(void* const* d_in, const int* in_sizes, int n_in,
                              void* d_out, int out_size) {
    const float* pred   = (const float*)d_in[0];   // (N, V, H, 1) f32
    const float* inputs = (const float*)d_in[1];   // (N, 80) f32
    float* out = (float*)d_out;

    loss_kernel<<<NPART, TPB>>>(pred, inputs, out);
}